// round 10
// baseline (speedup 1.0000x reference)
#include <cuda_runtime.h>
#include <cstdint>
#include <cstddef>

#define BB 16
#define MM 16
#define JXN 128
#define JQN 64
#define DN 256

// ---------------- smem layout (float indices), per CTA ≈ 109.8 KB -----------
constexpr int OFF_SP   = 0;       // sp [64][68]: C1, then P (tf32) = A of GEMM2
constexpr int OFF_ASD2 = 4352;    // A_s [64][68] chunk buf; reused as D2 in GEMM2
constexpr int OFF_W    = 8704;    // w1|w2|w3 (768)
constexpr int OFF_SU   = 9472;    // s_u[64]
constexpr int OFF_SH   = 9536;    // s_h[64]
constexpr int OFF_SPM  = 9600;    // s_pm[64]   (read by peer via DSMEM)
constexpr int OFF_PS   = 9664;    // p_s[128]
constexpr int OFF_PART = 9792;    // part: 4*64 float4 = 1024 floats
constexpr int OFF_UQD  = 10816;   // u_qd [64 q][260] tf32 (B of both GEMMs)
constexpr int SMEM_FLOATS = 27456;   // 109,824 B

__device__ __forceinline__ uint32_t f2t(float x) {
    uint32_t r;
    asm("cvt.rna.tf32.f32 %0, %1;" : "=r"(r) : "f"(x));
    return r;
}
__device__ __forceinline__ float f2tf(float x) { return __uint_as_float(f2t(x)); }

#define MMA_TF32(c, a, b)                                                       \
    asm volatile(                                                               \
        "mma.sync.aligned.m16n8k8.row.col.f32.tf32.tf32.f32 "                   \
        "{%0,%1,%2,%3}, {%4,%5,%6,%7}, {%8,%9}, {%0,%1,%2,%3};"                 \
        : "+f"((c)[0]), "+f"((c)[1]), "+f"((c)[2]), "+f"((c)[3])                \
        : "r"((a)[0]), "r"((a)[1]), "r"((a)[2]), "r"((a)[3]),                   \
          "r"((b)[0]), "r"((b)[1]))

__device__ __forceinline__ uint32_t smem_u32(const void* p) {
    uint32_t a;
    asm("{ .reg .u64 t; cvta.to.shared.u64 t, %1; cvt.u32.u64 %0, t; }" : "=r"(a) : "l"(p));
    return a;
}
__device__ __forceinline__ uint32_t mapa_rank(uint32_t addr, uint32_t rank) {
    uint32_t r;
    asm("mapa.shared::cluster.u32 %0, %1, %2;" : "=r"(r) : "r"(addr), "r"(rank));
    return r;
}
__device__ __forceinline__ float ld_cluster_f32(uint32_t addr) {
    float v;
    asm volatile("ld.shared::cluster.f32 %0, [%1];" : "=f"(v) : "r"(addr));
    return v;
}
#define CL_ARRIVE() asm volatile("barrier.cluster.arrive.aligned;" ::: "memory")
#define CL_WAIT()   asm volatile("barrier.cluster.wait.aligned;"   ::: "memory")

// ---------------------------------------------------------------------------
// Cluster of 2 CTAs = one (b,m); each CTA owns a 64-row j-half. 256 threads.
// ---------------------------------------------------------------------------
__global__ void __launch_bounds__(256, 2) __cluster_dims__(2, 1, 1)
attn_cl(const float* __restrict__ hg, const float* __restrict__ ug,
        const float* __restrict__ wg, float* __restrict__ out)
{
    extern __shared__ float smf[];
    float*  sp   = smf + OFF_SP;
    float*  AsD2 = smf + OFF_ASD2;
    float*  wsm  = smf + OFF_W;
    float*  s_u  = smf + OFF_SU;
    float*  s_h  = smf + OFF_SH;
    float*  s_pm = smf + OFF_SPM;
    float*  p_s  = smf + OFF_PS;
    float4* part = (float4*)(smf + OFF_PART);
    float*  u_qd = smf + OFF_UQD;

    const int tid  = threadIdx.x;
    const int wid  = tid >> 5;
    const int lane = tid & 31;
    const int g    = lane >> 2;
    const int t    = lane & 3;

    uint32_t rank;
    asm("mov.u32 %0, %%cluster_ctarank;" : "=r"(rank));
    const uint32_t peer = rank ^ 1u;
    const int bm   = blockIdx.x >> 1;
    const int half = (int)rank;           // which 64-row j-half we own
    const int b    = bm >> 4;

    const float* __restrict__ hbase = hg + (size_t)bm * JXN * DN;          // all 128 j
    const float* __restrict__ hrow  = hbase + (size_t)half * 64 * DN;      // own 64 j
    const float* __restrict__ ub    = ug + (size_t)b * JQN * DN;
    const size_t outbase = (size_t)bm * JXN * (4 * DN);

    const int wj = wid & 1;                              // j-tile group (2 x 32 rows)
    const int wn = wid >> 1;                             // n-tile group (4 x 16 cols)
    const int srow = tid >> 2, soff = (tid & 3) * 16;    // staging/softmax mapping

    // ---- early prefetch of GEMM1 chunk 0 ----
    float4 ph[4];
    #pragma unroll
    for (int i = 0; i < 4; i++)
        ph[i] = *(const float4*)(hrow + srow * DN + soff + 4 * i);

    // ---- stage w; stage u_qd (tf32, [q][d], stride 260) ----
    for (int i = tid; i < 3 * DN; i += 256) wsm[i] = wg[i];
    for (int idx = tid; idx < 64 * 64; idx += 256) {
        int q = idx >> 6, d4 = idx & 63;
        float4 v = *(const float4*)(ub + q * DN + d4 * 4);
        float* p = u_qd + q * 260 + d4 * 4;
        p[0] = f2tf(v.x); p[1] = f2tf(v.y); p[2] = f2tf(v.z); p[3] = f2tf(v.w);
    }
    // ---- s_u[q] = u[q,:] . w2 ----
    {
        int q = tid >> 2, sg = tid & 3;
        const float* up  = ub + q * DN + sg * 64;
        const float* w2p = wg + DN + sg * 64;
        float acc = 0.f;
        #pragma unroll 16
        for (int i = 0; i < 16; i++) {
            float4 a = *(const float4*)(up + 4 * i);
            float4 w = *(const float4*)(w2p + 4 * i);
            acc += a.x * w.x + a.y * w.y + a.z * w.z + a.w * w.w;
        }
        acc += __shfl_xor_sync(0xffffffffu, acc, 1, 4);
        acc += __shfl_xor_sync(0xffffffffu, acc, 2, 4);
        if (sg == 0) s_u[q] = acc;
    }
    __syncthreads();

    // ---- GEMM1: C1[64 j][64 q] = (h*w3).u^T, K=256 in 4 chunks of 64 ----
    float c1f[2][2][4];
    #pragma unroll
    for (int mt = 0; mt < 2; mt++)
        #pragma unroll
        for (int nt = 0; nt < 2; nt++)
            #pragma unroll
            for (int i = 0; i < 4; i++) c1f[mt][nt][i] = 0.f;

    float shp = 0.f;
    for (int c = 0; c < 4; c++) {
        #pragma unroll
        for (int i = 0; i < 4; i++) {
            const int dd = c * 64 + soff + 4 * i;
            float4 x = ph[i];
            const float* w1p = wsm + dd;
            shp += x.x * w1p[0] + x.y * w1p[1] + x.z * w1p[2] + x.w * w1p[3];
            const float* w3p = wsm + 2 * DN + dd;
            float* ap = AsD2 + srow * 68 + soff + 4 * i;
            ap[0] = f2tf(x.x * w3p[0]); ap[1] = f2tf(x.y * w3p[1]);
            ap[2] = f2tf(x.z * w3p[2]); ap[3] = f2tf(x.w * w3p[3]);
        }
        __syncthreads();
        if (c < 3) {
            #pragma unroll
            for (int i = 0; i < 4; i++)
                ph[i] = *(const float4*)(hrow + srow * DN + (c + 1) * 64 + soff + 4 * i);
        }
        #pragma unroll
        for (int it = 0; it < 8; it++) {
            const int kb = it * 8;
            uint32_t af[2][4], bf[2][2];
            #pragma unroll
            for (int mt = 0; mt < 2; mt++) {
                const float* ap = AsD2 + (wj * 32 + mt * 16 + g) * 68 + kb + t;
                af[mt][0] = __float_as_uint(ap[0]);
                af[mt][1] = __float_as_uint(ap[8 * 68]);
                af[mt][2] = __float_as_uint(ap[4]);
                af[mt][3] = __float_as_uint(ap[8 * 68 + 4]);
            }
            #pragma unroll
            for (int nt = 0; nt < 2; nt++) {
                const float* bp = u_qd + (wn * 16 + nt * 8 + g) * 260 + c * 64 + kb + t;
                bf[nt][0] = __float_as_uint(bp[0]);
                bf[nt][1] = __float_as_uint(bp[4]);
            }
            #pragma unroll
            for (int mt = 0; mt < 2; mt++)
                #pragma unroll
                for (int nt = 0; nt < 2; nt++)
                    MMA_TF32(c1f[mt][nt], af[mt], bf[nt]);
        }
        __syncthreads();   // A_s rewritten next iteration (single buffer)
    }

    // ---- s_h ----
    shp += __shfl_xor_sync(0xffffffffu, shp, 1, 4);
    shp += __shfl_xor_sync(0xffffffffu, shp, 2, 4);
    if ((tid & 3) == 0) s_h[srow] = shp;

    // ---- C1 fragments -> sp ----
    #pragma unroll
    for (int mt = 0; mt < 2; mt++)
        #pragma unroll
        for (int nt = 0; nt < 2; nt++) {
            float* cp = sp + (wj * 32 + mt * 16 + g) * 68 + wn * 16 + nt * 8 + 2 * t;
            *(float2*)cp            = make_float2(c1f[mt][nt][0], c1f[mt][nt][1]);
            *(float2*)(cp + 8 * 68) = make_float2(c1f[mt][nt][2], c1f[mt][nt][3]);
        }
    __syncthreads();

    // ---- softmax over q, in place; s_pm for own half ----
    {
        float v[16];
        #pragma unroll
        for (int i = 0; i < 16; i++) v[i] = sp[srow * 68 + soff + i] + s_u[soff + i];
        float mx = v[0];
        #pragma unroll
        for (int i = 1; i < 16; i++) mx = fmaxf(mx, v[i]);
        mx = fmaxf(mx, __shfl_xor_sync(0xffffffffu, mx, 1, 4));
        mx = fmaxf(mx, __shfl_xor_sync(0xffffffffu, mx, 2, 4));
        float sum = 0.f;
        #pragma unroll
        for (int i = 0; i < 16; i++) { v[i] = __expf(v[i] - mx); sum += v[i]; }
        sum += __shfl_xor_sync(0xffffffffu, sum, 1, 4);
        sum += __shfl_xor_sync(0xffffffffu, sum, 2, 4);
        float inv = 1.f / sum;
        #pragma unroll
        for (int i = 0; i < 16; i++) sp[srow * 68 + soff + i] = f2tf(v[i] * inv);
        if ((tid & 3) == 0) s_pm[srow] = mx + s_h[srow];
    }
    __syncthreads();
    // s_pm ready: release to peer; the cluster wait happens AFTER GEMM2 (overlap)
    CL_ARRIVE();

    // ---- GEMM2: u_att[64 j][256 d] = P . u, K=64(q), 4 d-slabs of 64 ----
    for (int s = 0; s < 4; s++) {
        float4 hpre[4];
        #pragma unroll
        for (int i = 0; i < 4; i++)
            hpre[i] = *(const float4*)(hrow + srow * DN + s * 64 + soff + 4 * i);

        float d2f[2][2][4];
        #pragma unroll
        for (int mt = 0; mt < 2; mt++)
            #pragma unroll
            for (int nt = 0; nt < 2; nt++)
                #pragma unroll
                for (int i = 0; i < 4; i++) d2f[mt][nt][i] = 0.f;

        #pragma unroll
        for (int it = 0; it < 8; it++) {
            const int kb = it * 8;
            uint32_t af[2][4], bf[2][2];
            #pragma unroll
            for (int mt = 0; mt < 2; mt++) {
                const float* ap = sp + (wj * 32 + mt * 16 + g) * 68 + kb + t;
                af[mt][0] = __float_as_uint(ap[0]);
                af[mt][1] = __float_as_uint(ap[8 * 68]);
                af[mt][2] = __float_as_uint(ap[4]);
                af[mt][3] = __float_as_uint(ap[8 * 68 + 4]);
            }
            #pragma unroll
            for (int nt = 0; nt < 2; nt++) {
                const float* bp = u_qd + (kb + t) * 260 + s * 64 + wn * 16 + nt * 8 + g;
                bf[nt][0] = __float_as_uint(bp[0]);
                bf[nt][1] = __float_as_uint(bp[4 * 260]);
            }
            #pragma unroll
            for (int mt = 0; mt < 2; mt++)
                #pragma unroll
                for (int nt = 0; nt < 2; nt++)
                    MMA_TF32(d2f[mt][nt], af[mt], bf[nt]);
        }
        __syncthreads();   // AsD2 free (chunk-MMA done) & prior epilogue LDS done
        #pragma unroll
        for (int mt = 0; mt < 2; mt++)
            #pragma unroll
            for (int nt = 0; nt < 2; nt++) {
                float* cp = AsD2 + (wj * 32 + mt * 16 + g) * 68 + wn * 16 + nt * 8 + 2 * t;
                *(float2*)cp            = make_float2(d2f[mt][nt][0], d2f[mt][nt][1]);
                *(float2*)(cp + 8 * 68) = make_float2(d2f[mt][nt][2], d2f[mt][nt][3]);
            }
        __syncthreads();
        {
            const int jgl = half * 64 + srow;
            float* ob = out + outbase + (size_t)jgl * (4 * DN);
            #pragma unroll
            for (int i = 0; i < 4; i++) {
                const int dl  = soff + 4 * i;
                const int dgl = s * 64 + dl;
                float4 ua = make_float4(AsD2[srow * 68 + dl + 0], AsD2[srow * 68 + dl + 1],
                                        AsD2[srow * 68 + dl + 2], AsD2[srow * 68 + dl + 3]);
                float4 h4 = hpre[i];
                float4 hu = make_float4(h4.x * ua.x, h4.y * ua.y, h4.z * ua.z, h4.w * ua.w);
                *(float4*)(ob + dgl)            = h4;
                *(float4*)(ob + DN + dgl)       = ua;
                *(float4*)(ob + 2 * DN + dgl)   = hu;
            }
        }
    }

    // ---- cluster wait (peer s_pm visible); p = softmax over all 128 j ----
    CL_WAIT();
    if (wid == 0) {
        const uint32_t la = smem_u32(s_pm) + lane * 4;
        const uint32_t ra = mapa_rank(la, peer);
        float v0 = s_pm[lane];
        float v1 = s_pm[lane + 32];
        float v2 = ld_cluster_f32(ra);
        float v3 = ld_cluster_f32(ra + 32 * 4);
        float mx = fmaxf(fmaxf(v0, v1), fmaxf(v2, v3));
        #pragma unroll
        for (int o = 16; o >= 1; o >>= 1) mx = fmaxf(mx, __shfl_xor_sync(0xffffffffu, mx, o));
        float e0 = __expf(v0 - mx), e1 = __expf(v1 - mx);
        float e2 = __expf(v2 - mx), e3 = __expf(v3 - mx);
        float sum = e0 + e1 + e2 + e3;
        #pragma unroll
        for (int o = 16; o >= 1; o >>= 1) sum += __shfl_xor_sync(0xffffffffu, sum, o);
        float inv = 1.f / sum;
        p_s[half * 64 + lane]      = e0 * inv;
        p_s[half * 64 + lane + 32] = e1 * inv;
        p_s[peer * 64 + lane]      = e2 * inv;
        p_s[peer * 64 + lane + 32] = e3 * inv;
    }
    __syncthreads();     // p_s ready; warp0's remote reads complete
    CL_ARRIVE();         // signal: done reading peer smem (final wait before exit)

    // ---- h_att = sum over ALL 128 j of p_j h[j,:]; write own seg-3 half ----
    {
        const int jg = tid >> 6, dq = tid & 63;   // 4 j-groups x 32 j
        float4 acc = make_float4(0.f, 0.f, 0.f, 0.f);
        #pragma unroll 4
        for (int j = jg * 32; j < jg * 32 + 32; j++) {
            float4 hv = *(const float4*)(hbase + (size_t)j * DN + dq * 4);
            float pj = p_s[j];
            acc.x += pj * hv.x; acc.y += pj * hv.y; acc.z += pj * hv.z; acc.w += pj * hv.w;
        }
        part[jg * 64 + dq] = acc;
        __syncthreads();
        if (tid < 64) {
            float4 sacc = part[tid];
            #pragma unroll
            for (int gg = 1; gg < 4; gg++) {
                float4 v = part[gg * 64 + tid];
                sacc.x += v.x; sacc.y += v.y; sacc.z += v.z; sacc.w += v.w;
            }
            part[tid] = sacc;
        }
        __syncthreads();
        const float4 ha = part[dq];
        #pragma unroll 2
        for (int jl = jg * 16; jl < jg * 16 + 16; jl++) {
            const int jgl = half * 64 + jl;
            float4 hv = *(const float4*)(hbase + (size_t)jgl * DN + dq * 4);
            float4 o;
            o.x = hv.x * ha.x; o.y = hv.y * ha.y; o.z = hv.z * ha.z; o.w = hv.w * ha.w;
            *(float4*)(out + outbase + (size_t)jgl * (4 * DN) + 3 * DN + dq * 4) = o;
        }
    }

    CL_WAIT();   // don't exit while peer may still read our s_pm
}

// ---------------------------------------------------------------------------
extern "C" void kernel_launch(void* const* d_in, const int* in_sizes, int n_in,
                              void* d_out, int out_size)
{
    (void)in_sizes; (void)n_in; (void)out_size;
    const float* h = (const float*)d_in[0];
    const float* u = (const float*)d_in[1];
    const float* w = (const float*)d_in[2];
    // d_in[3] (scalar bias b) cancels in both softmaxes -> unused.
    float* out = (float*)d_out;

    const size_t smem = SMEM_FLOATS * sizeof(float);   // 109,824 B
    cudaFuncSetAttribute(attn_cl, cudaFuncAttributeMaxDynamicSharedMemorySize, (int)smem);
    attn_cl<<<BB * MM * 2, 256, smem>>>(h, u, w, out);
}

// round 11
// speedup vs baseline: 1.2031x; 1.2031x over previous
#include <cuda_runtime.h>
#include <cuda_fp16.h>
#include <cstdint>
#include <cstddef>

#define BB 16
#define MM 16
#define JXN 128
#define JQN 64
#define DN 256

// ---------------- smem layout (byte offsets) ---------------------------------
constexpr int OFF_C1  = 0;        // fp32 [128][68] C1; reused as D2 bounce in GEMM2
constexpr int OFF_UH  = 34816;    // half [64 q][264 d]   (B of GEMM1, [n][k])
constexpr int OFF_UT  = 68608;    // half [256 d][72 q]   (B of GEMM2, [n][k])
constexpr int OFF_AS  = 105472;   // half 2 x [128 j][72 d] (A chunks, dbl-buffered)
constexpr int OFF_PH  = 142336;   // half [128 j][72 q]   (P = A of GEMM2)
constexpr int OFF_W   = 160768;   // fp32 w1|w2|w3 (768)
constexpr int OFF_SU  = 163840;   // fp32 s_u[64]
constexpr int OFF_SH  = 164096;   // fp32 s_h[128]
constexpr int OFF_SPM = 164608;   // fp32 s_pm[128]
constexpr int OFF_PS  = 165120;   // fp32 p_s[128]
constexpr int OFF_PART= 165632;   // float4 part[8][64] = 8192 B
constexpr int SMEM_BYTES = 173824;

// m16n8k16 fp16 mma, fp32 accum (base sm_80+ ISA; valid on compute_103)
#define MMA_F16(c, a, b)                                                        \
    asm volatile(                                                               \
        "mma.sync.aligned.m16n8k16.row.col.f32.f16.f16.f32 "                    \
        "{%0,%1,%2,%3}, {%4,%5,%6,%7}, {%8,%9}, {%0,%1,%2,%3};"                 \
        : "+f"((c)[0]), "+f"((c)[1]), "+f"((c)[2]), "+f"((c)[3])                \
        : "r"((a)[0]), "r"((a)[1]), "r"((a)[2]), "r"((a)[3]),                   \
          "r"((b)[0]), "r"((b)[1]))

__device__ __forceinline__ uint32_t pack_h2(float a, float b) {
    __half2 h = __floats2half2_rn(a, b);   // low = a, high = b
    return *(uint32_t*)&h;
}

// ---------------------------------------------------------------------------
// Fused kernel, CTA = one (b,m). 512 threads, mma.sync fp16 (f32 accum).
// ---------------------------------------------------------------------------
__global__ void __launch_bounds__(512, 1)
attn_h16(const float* __restrict__ hg, const float* __restrict__ ug,
         const float* __restrict__ wg, float* __restrict__ out)
{
    extern __shared__ __align__(16) char smc[];
    float*  sp   = (float*)(smc + OFF_C1);    // C1 / D2
    __half* u_h  = (__half*)(smc + OFF_UH);
    __half* u_t  = (__half*)(smc + OFF_UT);
    __half* P_h  = (__half*)(smc + OFF_PH);
    float*  wsm  = (float*)(smc + OFF_W);
    float*  s_u  = (float*)(smc + OFF_SU);
    float*  s_h  = (float*)(smc + OFF_SH);
    float*  s_pm = (float*)(smc + OFF_SPM);
    float*  p_s  = (float*)(smc + OFF_PS);
    float4* part = (float4*)(smc + OFF_PART);

    const int tid  = threadIdx.x;
    const int wid  = tid >> 5;
    const int lane = tid & 31;
    const int g    = lane >> 2;
    const int t    = lane & 3;
    const int bm   = blockIdx.x;
    const int b    = bm >> 4;

    const float* __restrict__ hrow = hg + (size_t)bm * JXN * DN;
    const float* __restrict__ ub   = ug + (size_t)b * JQN * DN;
    const size_t outbase = (size_t)bm * JXN * (4 * DN);

    const int wj = wid & 3;                              // j-tile group (4 x 32)
    const int wn = wid >> 2;                             // n-tile group (4 x 16)
    const int srow = tid >> 2, soff = (tid & 3) * 16;    // staging/softmax mapping

    // ---- early prefetch of GEMM1 chunk 0 ----
    float4 ph[4];
    #pragma unroll
    for (int i = 0; i < 4; i++)
        ph[i] = *(const float4*)(hrow + srow * DN + soff + 4 * i);

    // ---- stage w; stage u_h [q][264] + u_t [d][72] halves ----
    for (int i = tid; i < 3 * DN; i += 512) wsm[i] = wg[i];
    for (int idx = tid; idx < 64 * 64; idx += 512) {
        int q = idx >> 6, d4 = idx & 63;
        float4 v = *(const float4*)(ub + q * DN + d4 * 4);
        uint2 pk = make_uint2(pack_h2(v.x, v.y), pack_h2(v.z, v.w));
        *(uint2*)((char*)u_h + q * 528 + d4 * 8) = pk;
        const int d0 = d4 * 4;
        u_t[(d0 + 0) * 72 + q] = __float2half_rn(v.x);
        u_t[(d0 + 1) * 72 + q] = __float2half_rn(v.y);
        u_t[(d0 + 2) * 72 + q] = __float2half_rn(v.z);
        u_t[(d0 + 3) * 72 + q] = __float2half_rn(v.w);
    }
    // ---- s_u[q] = u[q,:] . w2 (fp32 from gmem; 4 lanes per q) ----
    {
        int q = tid >> 2, sg = tid & 3;
        const float* up  = ub + q * DN + sg * 64;
        const float* w2p = wg + DN + sg * 64;
        float acc = 0.f;
        #pragma unroll 16
        for (int i = 0; i < 16; i++) {
            float4 a = *(const float4*)(up + 4 * i);
            float4 w = *(const float4*)(w2p + 4 * i);
            acc += a.x * w.x + a.y * w.y + a.z * w.z + a.w * w.w;
        }
        acc += __shfl_xor_sync(0xffffffffu, acc, 1, 4);
        acc += __shfl_xor_sync(0xffffffffu, acc, 2, 4);
        if (sg == 0) s_u[q] = acc;
    }
    __syncthreads();

    // ---- GEMM1: C1[128 j][64 q] = (h*w3).u^T, K=256 in 4 chunks of 64 ----
    float c1f[2][2][4];
    #pragma unroll
    for (int mt = 0; mt < 2; mt++)
        #pragma unroll
        for (int nt = 0; nt < 2; nt++)
            #pragma unroll
            for (int i = 0; i < 4; i++) c1f[mt][nt][i] = 0.f;

    float shp = 0.f;
    for (int c = 0; c < 4; c++) {
        __half* Ab = (__half*)(smc + OFF_AS + (c & 1) * 18432);
        // s_h partial + fp16 scale/stage from prefetched regs
        {
            uint4 st0, st1;
            uint32_t* s0 = (uint32_t*)&st0;
            uint32_t* s1 = (uint32_t*)&st1;
            #pragma unroll
            for (int i = 0; i < 4; i++) {
                const int dd = c * 64 + soff + 4 * i;
                float4 x = ph[i];
                const float* w1p = wsm + dd;
                shp += x.x * w1p[0] + x.y * w1p[1] + x.z * w1p[2] + x.w * w1p[3];
                const float* w3p = wsm + 2 * DN + dd;
                uint32_t* dstp = (i < 2) ? (s0 + 2 * i) : (s1 + 2 * (i - 2));
                dstp[0] = pack_h2(x.x * w3p[0], x.y * w3p[1]);
                dstp[1] = pack_h2(x.z * w3p[2], x.w * w3p[3]);
            }
            *(uint4*)((char*)Ab + srow * 144 + soff * 2)      = st0;
            *(uint4*)((char*)Ab + srow * 144 + soff * 2 + 16) = st1;
        }
        __syncthreads();
        if (c < 3) {
            #pragma unroll
            for (int i = 0; i < 4; i++)
                ph[i] = *(const float4*)(hrow + srow * DN + (c + 1) * 64 + soff + 4 * i);
        }
        #pragma unroll
        for (int it = 0; it < 4; it++) {
            const int kb = it * 16;
            uint32_t af[2][4], bf[2][2];
            #pragma unroll
            for (int mt = 0; mt < 2; mt++) {
                const __half* ap = Ab + (wj * 32 + mt * 16 + g) * 72 + kb + 2 * t;
                af[mt][0] = *(const uint32_t*)ap;
                af[mt][1] = *(const uint32_t*)(ap + 8 * 72);
                af[mt][2] = *(const uint32_t*)(ap + 8);
                af[mt][3] = *(const uint32_t*)(ap + 8 * 72 + 8);
            }
            #pragma unroll
            for (int nt = 0; nt < 2; nt++) {
                const __half* bp = u_h + (wn * 16 + nt * 8 + g) * 264 + c * 64 + kb + 2 * t;
                bf[nt][0] = *(const uint32_t*)bp;
                bf[nt][1] = *(const uint32_t*)(bp + 8);
            }
            #pragma unroll
            for (int mt = 0; mt < 2; mt++)
                #pragma unroll
                for (int nt = 0; nt < 2; nt++)
                    MMA_F16(c1f[mt][nt], af[mt], bf[nt]);
        }
        // no trailing sync: next STS targets the other buffer
    }

    // ---- s_h ----
    shp += __shfl_xor_sync(0xffffffffu, shp, 1, 4);
    shp += __shfl_xor_sync(0xffffffffu, shp, 2, 4);
    if ((tid & 3) == 0) s_h[srow] = shp;

    // ---- C1 fragments -> sp (fp32) ----
    #pragma unroll
    for (int mt = 0; mt < 2; mt++)
        #pragma unroll
        for (int nt = 0; nt < 2; nt++) {
            float* cp = sp + (wj * 32 + mt * 16 + g) * 68 + wn * 16 + nt * 8 + 2 * t;
            *(float2*)cp            = make_float2(c1f[mt][nt][0], c1f[mt][nt][1]);
            *(float2*)(cp + 8 * 68) = make_float2(c1f[mt][nt][2], c1f[mt][nt][3]);
        }
    __syncthreads();

    // ---- softmax over q (thread: row srow, 16 q at soff); write P_h fp16 ----
    {
        float v[16];
        #pragma unroll
        for (int i = 0; i < 16; i++) v[i] = sp[srow * 68 + soff + i] + s_u[soff + i];
        float mx = v[0];
        #pragma unroll
        for (int i = 1; i < 16; i++) mx = fmaxf(mx, v[i]);
        mx = fmaxf(mx, __shfl_xor_sync(0xffffffffu, mx, 1, 4));
        mx = fmaxf(mx, __shfl_xor_sync(0xffffffffu, mx, 2, 4));
        float sum = 0.f;
        #pragma unroll
        for (int i = 0; i < 16; i++) { v[i] = __expf(v[i] - mx); sum += v[i]; }
        sum += __shfl_xor_sync(0xffffffffu, sum, 1, 4);
        sum += __shfl_xor_sync(0xffffffffu, sum, 2, 4);
        float inv = 1.f / sum;
        uint4 st0, st1;
        uint32_t* s0 = (uint32_t*)&st0;
        uint32_t* s1 = (uint32_t*)&st1;
        #pragma unroll
        for (int i = 0; i < 4; i++) {
            uint32_t* dstp = (i < 2) ? (s0 + 2 * i) : (s1 + 2 * (i - 2));
            dstp[0] = pack_h2(v[4 * i + 0] * inv, v[4 * i + 1] * inv);
            dstp[1] = pack_h2(v[4 * i + 2] * inv, v[4 * i + 3] * inv);
        }
        *(uint4*)((char*)P_h + srow * 144 + soff * 2)      = st0;
        *(uint4*)((char*)P_h + srow * 144 + soff * 2 + 16) = st1;
        if ((tid & 3) == 0) s_pm[srow] = mx + s_h[srow];
    }
    __syncthreads();

    // ---- p = softmax_j(s_pm) (warp 0; overlaps others entering GEMM2) ----
    if (wid == 0) {
        float v0 = s_pm[lane], v1 = s_pm[lane + 32], v2 = s_pm[lane + 64], v3 = s_pm[lane + 96];
        float mx = fmaxf(fmaxf(v0, v1), fmaxf(v2, v3));
        #pragma unroll
        for (int o = 16; o >= 1; o >>= 1) mx = fmaxf(mx, __shfl_xor_sync(0xffffffffu, mx, o));
        float e0 = __expf(v0 - mx), e1 = __expf(v1 - mx);
        float e2 = __expf(v2 - mx), e3 = __expf(v3 - mx);
        float s = e0 + e1 + e2 + e3;
        #pragma unroll
        for (int o = 16; o >= 1; o >>= 1) s += __shfl_xor_sync(0xffffffffu, s, o);
        float inv = 1.f / s;
        p_s[lane] = e0 * inv; p_s[lane + 32] = e1 * inv;
        p_s[lane + 64] = e2 * inv; p_s[lane + 96] = e3 * inv;
    }

    // ---- GEMM2: u_att[128 j][256 d] = P . u, K=64(q), 4 d-slabs of 64 ----
    for (int s = 0; s < 4; s++) {
        float4 hpre[4];
        #pragma unroll
        for (int i = 0; i < 4; i++)
            hpre[i] = *(const float4*)(hrow + srow * DN + s * 64 + soff + 4 * i);

        float d2f[2][2][4];
        #pragma unroll
        for (int mt = 0; mt < 2; mt++)
            #pragma unroll
            for (int nt = 0; nt < 2; nt++)
                #pragma unroll
                for (int i = 0; i < 4; i++) d2f[mt][nt][i] = 0.f;

        #pragma unroll
        for (int it = 0; it < 4; it++) {
            const int kb = it * 16;
            uint32_t af[2][4], bf[2][2];
            #pragma unroll
            for (int mt = 0; mt < 2; mt++) {
                const __half* ap = P_h + (wj * 32 + mt * 16 + g) * 72 + kb + 2 * t;
                af[mt][0] = *(const uint32_t*)ap;
                af[mt][1] = *(const uint32_t*)(ap + 8 * 72);
                af[mt][2] = *(const uint32_t*)(ap + 8);
                af[mt][3] = *(const uint32_t*)(ap + 8 * 72 + 8);
            }
            #pragma unroll
            for (int nt = 0; nt < 2; nt++) {
                const __half* bp = u_t + (s * 64 + wn * 16 + nt * 8 + g) * 72 + kb + 2 * t;
                bf[nt][0] = *(const uint32_t*)bp;
                bf[nt][1] = *(const uint32_t*)(bp + 8);
            }
            #pragma unroll
            for (int mt = 0; mt < 2; mt++)
                #pragma unroll
                for (int nt = 0; nt < 2; nt++)
                    MMA_F16(d2f[mt][nt], af[mt], bf[nt]);
        }
        __syncthreads();   // sp (C1/D2) readers from prior phase done
        #pragma unroll
        for (int mt = 0; mt < 2; mt++)
            #pragma unroll
            for (int nt = 0; nt < 2; nt++) {
                float* cp = sp + (wj * 32 + mt * 16 + g) * 68 + wn * 16 + nt * 8 + 2 * t;
                *(float2*)cp            = make_float2(d2f[mt][nt][0], d2f[mt][nt][1]);
                *(float2*)(cp + 8 * 68) = make_float2(d2f[mt][nt][2], d2f[mt][nt][3]);
            }
        __syncthreads();
        {
            float* ob = out + outbase + (size_t)srow * (4 * DN);
            #pragma unroll
            for (int i = 0; i < 4; i++) {
                const int dl  = soff + 4 * i;
                const int dgl = s * 64 + dl;
                float4 ua = make_float4(sp[srow * 68 + dl + 0], sp[srow * 68 + dl + 1],
                                        sp[srow * 68 + dl + 2], sp[srow * 68 + dl + 3]);
                float4 h4 = hpre[i];
                float4 hu = make_float4(h4.x * ua.x, h4.y * ua.y, h4.z * ua.z, h4.w * ua.w);
                *(float4*)(ob + dgl)            = h4;   // segment 0: h
                *(float4*)(ob + DN + dgl)       = ua;   // segment 1: u_att
                *(float4*)(ob + 2 * DN + dgl)   = hu;   // segment 2: h*u_att
            }
        }
    }
    __syncthreads();

    // ---- h_att = sum_j p_j h[j,:]; write segment 3 ----
    {
        const int jg = tid >> 6, dq = tid & 63;
        float4 acc = make_float4(0.f, 0.f, 0.f, 0.f);
        #pragma unroll 4
        for (int j = jg * 16; j < jg * 16 + 16; j++) {
            float4 hv = *(const float4*)(hrow + j * DN + dq * 4);
            float pj = p_s[j];
            acc.x += pj * hv.x; acc.y += pj * hv.y; acc.z += pj * hv.z; acc.w += pj * hv.w;
        }
        part[jg * 64 + dq] = acc;
        __syncthreads();
        if (tid < 64) {
            float4 sacc = part[tid];
            #pragma unroll
            for (int gg = 1; gg < 8; gg++) {
                float4 v = part[gg * 64 + tid];
                sacc.x += v.x; sacc.y += v.y; sacc.z += v.z; sacc.w += v.w;
            }
            part[tid] = sacc;
        }
        __syncthreads();
        const float4 ha = part[dq];
        #pragma unroll 2
        for (int j = jg * 16; j < jg * 16 + 16; j++) {
            float4 hv = *(const float4*)(hrow + j * DN + dq * 4);
            float4 o;
            o.x = hv.x * ha.x; o.y = hv.y * ha.y; o.z = hv.z * ha.z; o.w = hv.w * ha.w;
            *(float4*)(out + outbase + (size_t)j * (4 * DN) + 3 * DN + dq * 4) = o;
        }
    }
}

// ---------------------------------------------------------------------------
extern "C" void kernel_launch(void* const* d_in, const int* in_sizes, int n_in,
                              void* d_out, int out_size)
{
    (void)in_sizes; (void)n_in; (void)out_size;
    const float* h = (const float*)d_in[0];
    const float* u = (const float*)d_in[1];
    const float* w = (const float*)d_in[2];
    // d_in[3] (scalar bias b) cancels in both softmaxes -> unused.
    float* out = (float*)d_out;

    cudaFuncSetAttribute(attn_h16, cudaFuncAttributeMaxDynamicSharedMemorySize, SMEM_BYTES);
    attn_h16<<<BB * MM, 512, SMEM_BYTES>>>(h, u, w, out);
}

// round 12
// speedup vs baseline: 1.3925x; 1.1574x over previous
#include <cuda_runtime.h>
#include <cuda_fp16.h>
#include <cstdint>
#include <cstddef>

#define BB 16
#define MM 16
#define JXN 128
#define JQN 64
#define DN 256

// ---------------- smem layout (byte offsets) ---------------------------------
constexpr int OFF_C1  = 0;        // fp32 [128][68] C1 scratch (34816)
constexpr int OFF_UH  = 34816;    // half [64 q][264 d]  (B of GEMM1)      33792
constexpr int OFF_UH2 = 68608;    // u32  [32 qp][264 d] (B of GEMM2)      33792
constexpr int OFF_AS  = 102400;   // half 2 x [128 j][72 d] (A chunks)     36864
constexpr int OFF_PH  = 139264;   // half [128 j][72 q]  (P = A of GEMM2)  18432
constexpr int OFF_W   = 157696;   // fp32 w1|w2|w3 (3072)
constexpr int OFF_SU  = 160768;   // fp32 s_u[64]
constexpr int OFF_SH  = 161024;   // fp32 s_h[128]
constexpr int OFF_SPM = 161536;   // fp32 s_pm[128]
constexpr int OFF_PS  = 162048;   // fp32 p_s[128]
constexpr int OFF_PART= 162560;   // float4 part[8][64] = 8192
constexpr int SMEM_BYTES = 170752;

#define MMA_F16(c, a, b)                                                        \
    asm volatile(                                                               \
        "mma.sync.aligned.m16n8k16.row.col.f32.f16.f16.f32 "                    \
        "{%0,%1,%2,%3}, {%4,%5,%6,%7}, {%8,%9}, {%0,%1,%2,%3};"                 \
        : "+f"((c)[0]), "+f"((c)[1]), "+f"((c)[2]), "+f"((c)[3])                \
        : "r"((a)[0]), "r"((a)[1]), "r"((a)[2]), "r"((a)[3]),                   \
          "r"((b)[0]), "r"((b)[1]))

__device__ __forceinline__ uint32_t pack_h2(float a, float b) {
    __half2 h = __floats2half2_rn(a, b);   // low = a, high = b
    return *(uint32_t*)&h;
}
#define NBAR(id, cnt) asm volatile("bar.sync %0, %1;" :: "r"(id), "r"(cnt) : "memory")

// ---------------------------------------------------------------------------
// Fused kernel, CTA = one (b,m). 512 threads, mma.sync fp16 (f32 accum).
// ---------------------------------------------------------------------------
__global__ void __launch_bounds__(512, 1)
attn_h16(const float* __restrict__ hg, const float* __restrict__ ug,
         const float* __restrict__ wg, float* __restrict__ out)
{
    extern __shared__ __align__(16) char smc[];
    float*    sp   = (float*)(smc + OFF_C1);
    __half*   u_h  = (__half*)(smc + OFF_UH);
    uint32_t* u_h2 = (uint32_t*)(smc + OFF_UH2);
    __half*   P_h  = (__half*)(smc + OFF_PH);
    float*    wsm  = (float*)(smc + OFF_W);
    float*    s_u  = (float*)(smc + OFF_SU);
    float*    s_h  = (float*)(smc + OFF_SH);
    float*    s_pm = (float*)(smc + OFF_SPM);
    float*    p_s  = (float*)(smc + OFF_PS);
    float4*   part = (float4*)(smc + OFF_PART);

    const int tid  = threadIdx.x;
    const int wid  = tid >> 5;
    const int lane = tid & 31;
    const int g    = lane >> 2;
    const int t    = lane & 3;
    const int bm   = blockIdx.x;
    const int b    = bm >> 4;

    const float* __restrict__ hrow = hg + (size_t)bm * JXN * DN;
    const float* __restrict__ ub   = ug + (size_t)b * JQN * DN;
    const size_t outbase = (size_t)bm * JXN * (4 * DN);

    const int wj = wid & 3;                              // j-tile group (4 x 32)
    const int wn = wid >> 2;                             // n-tile group
    const int srow = tid >> 2, soff = (tid & 3) * 16;    // staging mapping

    // ---- early prefetch of GEMM1 chunk 0 ----
    float4 ph[4];
    #pragma unroll
    for (int i = 0; i < 4; i++)
        ph[i] = *(const float4*)(hrow + srow * DN + soff + 4 * i);

    // ---- stage w; u_h [q][264]; u_h2 [q-pair][264] (all conflict-free) ----
    for (int i = tid; i < 3 * DN; i += 512) wsm[i] = wg[i];
    for (int idx = tid; idx < 64 * 64; idx += 512) {
        int q = idx >> 6, d4 = idx & 63;
        float4 v = *(const float4*)(ub + q * DN + d4 * 4);
        *(uint2*)((char*)u_h + q * 528 + d4 * 8) =
            make_uint2(pack_h2(v.x, v.y), pack_h2(v.z, v.w));
    }
    for (int idx = tid; idx < 32 * 256; idx += 512) {
        int q2 = idx >> 8, d = idx & 255;
        float a = ub[(2 * q2) * DN + d];
        float c = ub[(2 * q2 + 1) * DN + d];
        u_h2[q2 * 264 + d] = pack_h2(a, c);   // low = even q
    }
    // ---- s_u[q] = u[q,:] . w2 ----
    {
        int q = tid >> 2, sg = tid & 3;
        const float* up  = ub + q * DN + sg * 64;
        const float* w2p = wg + DN + sg * 64;
        float acc = 0.f;
        #pragma unroll 16
        for (int i = 0; i < 16; i++) {
            float4 a = *(const float4*)(up + 4 * i);
            float4 w = *(const float4*)(w2p + 4 * i);
            acc += a.x * w.x + a.y * w.y + a.z * w.z + a.w * w.w;
        }
        acc += __shfl_xor_sync(0xffffffffu, acc, 1, 4);
        acc += __shfl_xor_sync(0xffffffffu, acc, 2, 4);
        if (sg == 0) s_u[q] = acc;
    }
    __syncthreads();

    // ---- GEMM1: C1[128 j][64 q] = (h*w3).u^T, K=256, 4 chunks, dbl-buffer ----
    float c1f[2][2][4];
    #pragma unroll
    for (int mt = 0; mt < 2; mt++)
        #pragma unroll
        for (int nt = 0; nt < 2; nt++)
            #pragma unroll
            for (int i = 0; i < 4; i++) c1f[mt][nt][i] = 0.f;

    float shp = 0.f;
    for (int c = 0; c < 4; c++) {
        __half* Ab = (__half*)(smc + OFF_AS + (c & 1) * 18432);
        {
            uint4 st0, st1;
            uint32_t* s0 = (uint32_t*)&st0;
            uint32_t* s1 = (uint32_t*)&st1;
            #pragma unroll
            for (int i = 0; i < 4; i++) {
                const int dd = c * 64 + soff + 4 * i;
                float4 x = ph[i];
                const float* w1p = wsm + dd;
                shp += x.x * w1p[0] + x.y * w1p[1] + x.z * w1p[2] + x.w * w1p[3];
                const float* w3p = wsm + 2 * DN + dd;
                uint32_t* dstp = (i < 2) ? (s0 + 2 * i) : (s1 + 2 * (i - 2));
                dstp[0] = pack_h2(x.x * w3p[0], x.y * w3p[1]);
                dstp[1] = pack_h2(x.z * w3p[2], x.w * w3p[3]);
            }
            *(uint4*)((char*)Ab + srow * 144 + soff * 2)      = st0;
            *(uint4*)((char*)Ab + srow * 144 + soff * 2 + 16) = st1;
        }
        __syncthreads();
        if (c < 3) {
            #pragma unroll
            for (int i = 0; i < 4; i++)
                ph[i] = *(const float4*)(hrow + srow * DN + (c + 1) * 64 + soff + 4 * i);
        }
        #pragma unroll
        for (int it = 0; it < 4; it++) {
            const int kb = it * 16;
            uint32_t af[2][4], bf[2][2];
            #pragma unroll
            for (int mt = 0; mt < 2; mt++) {
                const __half* ap = Ab + (wj * 32 + mt * 16 + g) * 72 + kb + 2 * t;
                af[mt][0] = *(const uint32_t*)ap;
                af[mt][1] = *(const uint32_t*)(ap + 8 * 72);
                af[mt][2] = *(const uint32_t*)(ap + 8);
                af[mt][3] = *(const uint32_t*)(ap + 8 * 72 + 8);
            }
            #pragma unroll
            for (int nt = 0; nt < 2; nt++) {
                const __half* bp = u_h + (wn * 16 + nt * 8 + g) * 264 + c * 64 + kb + 2 * t;
                bf[nt][0] = *(const uint32_t*)bp;
                bf[nt][1] = *(const uint32_t*)(bp + 8);
            }
            #pragma unroll
            for (int mt = 0; mt < 2; mt++)
                #pragma unroll
                for (int nt = 0; nt < 2; nt++)
                    MMA_F16(c1f[mt][nt], af[mt], bf[nt]);
        }
    }

    // ---- s_h ----
    shp += __shfl_xor_sync(0xffffffffu, shp, 1, 4);
    shp += __shfl_xor_sync(0xffffffffu, shp, 2, 4);
    if ((tid & 3) == 0) s_h[srow] = shp;

    // ---- C1 fragments -> sp (fp32) ----
    #pragma unroll
    for (int mt = 0; mt < 2; mt++)
        #pragma unroll
        for (int nt = 0; nt < 2; nt++) {
            float* cp = sp + (wj * 32 + mt * 16 + g) * 68 + wn * 16 + nt * 8 + 2 * t;
            *(float2*)cp            = make_float2(c1f[mt][nt][0], c1f[mt][nt][1]);
            *(float2*)(cp + 8 * 68) = make_float2(c1f[mt][nt][2], c1f[mt][nt][3]);
        }
    __syncthreads();

    // ---- softmax over q, warp-group aligned: warp handles 8 rows of its own
    //      wj-group (rows 32*wj + 8*wn + r'); writes P_h fp16 + s_pm ----
    {
        const int r2 = 32 * wj + 8 * wn + (lane >> 2);
        const int o2 = (lane & 3) * 16;
        float v[16];
        #pragma unroll
        for (int i = 0; i < 16; i++) v[i] = sp[r2 * 68 + o2 + i] + s_u[o2 + i];
        float mx = v[0];
        #pragma unroll
        for (int i = 1; i < 16; i++) mx = fmaxf(mx, v[i]);
        mx = fmaxf(mx, __shfl_xor_sync(0xffffffffu, mx, 1, 4));
        mx = fmaxf(mx, __shfl_xor_sync(0xffffffffu, mx, 2, 4));
        float sum = 0.f;
        #pragma unroll
        for (int i = 0; i < 16; i++) { v[i] = __expf(v[i] - mx); sum += v[i]; }
        sum += __shfl_xor_sync(0xffffffffu, sum, 1, 4);
        sum += __shfl_xor_sync(0xffffffffu, sum, 2, 4);
        float inv = 1.f / sum;
        uint4 st0, st1;
        uint32_t* s0 = (uint32_t*)&st0;
        uint32_t* s1 = (uint32_t*)&st1;
        #pragma unroll
        for (int i = 0; i < 4; i++) {
            uint32_t* dstp = (i < 2) ? (s0 + 2 * i) : (s1 + 2 * (i - 2));
            dstp[0] = pack_h2(v[4 * i + 0] * inv, v[4 * i + 1] * inv);
            dstp[1] = pack_h2(v[4 * i + 2] * inv, v[4 * i + 3] * inv);
        }
        *(uint4*)((char*)P_h + r2 * 144 + o2 * 2)      = st0;
        *(uint4*)((char*)P_h + r2 * 144 + o2 * 2 + 16) = st1;
        if ((lane & 3) == 0) s_pm[r2] = mx + s_h[r2];
    }
    // group barrier: the 4 warps sharing wj exchange their P rows
    NBAR(1 + wj, 128);

    // ---- GEMM2 (barrier-free): u_att[rows 32wj..+31][all 256 d] = P . u ----
    float d2f[2][8][4];
    #pragma unroll
    for (int mt = 0; mt < 2; mt++)
        #pragma unroll
        for (int nt = 0; nt < 8; nt++)
            #pragma unroll
            for (int i = 0; i < 4; i++) d2f[mt][nt][i] = 0.f;

    #pragma unroll
    for (int it = 0; it < 4; it++) {
        const int kb = it * 16;
        uint32_t af[2][4];
        #pragma unroll
        for (int mt = 0; mt < 2; mt++) {
            const __half* ap = P_h + (wj * 32 + mt * 16 + g) * 72 + kb + 2 * t;
            af[mt][0] = *(const uint32_t*)ap;
            af[mt][1] = *(const uint32_t*)(ap + 8 * 72);
            af[mt][2] = *(const uint32_t*)(ap + 8);
            af[mt][3] = *(const uint32_t*)(ap + 8 * 72 + 8);
        }
        #pragma unroll
        for (int nt = 0; nt < 8; nt++) {
            const int dcol = wn * 64 + nt * 8 + g;
            uint32_t bf[2];
            bf[0] = u_h2[(it * 8 + t) * 264 + dcol];
            bf[1] = u_h2[(it * 8 + t + 4) * 264 + dcol];
            MMA_F16(d2f[0][nt], af[0], bf);
            MMA_F16(d2f[1][nt], af[1], bf);
        }
    }

    // ---- direct epilogue: segments 1,2 via STG.64 (quad = full 32B sector) ----
    #pragma unroll
    for (int mt = 0; mt < 2; mt++) {
        const int R0 = wj * 32 + mt * 16 + g;
        const int R1 = R0 + 8;
        float* ob0 = out + outbase + (size_t)R0 * (4 * DN);
        float* ob1 = out + outbase + (size_t)R1 * (4 * DN);
        const float* h0 = hrow + R0 * DN;
        const float* h1 = hrow + R1 * DN;
        #pragma unroll
        for (int nt = 0; nt < 8; nt++) {
            const int d = wn * 64 + nt * 8 + 2 * t;
            float2 hv0 = *(const float2*)(h0 + d);
            float2 hv1 = *(const float2*)(h1 + d);
            float2 ua0 = make_float2(d2f[mt][nt][0], d2f[mt][nt][1]);
            float2 ua1 = make_float2(d2f[mt][nt][2], d2f[mt][nt][3]);
            *(float2*)(ob0 + DN + d)     = ua0;
            *(float2*)(ob0 + 2 * DN + d) = make_float2(hv0.x * ua0.x, hv0.y * ua0.y);
            *(float2*)(ob1 + DN + d)     = ua1;
            *(float2*)(ob1 + 2 * DN + d) = make_float2(hv1.x * ua1.x, hv1.y * ua1.y);
        }
    }
    __syncthreads();

    // ---- p = softmax_j(s_pm) (warp 0) ----
    if (wid == 0) {
        float v0 = s_pm[lane], v1 = s_pm[lane + 32], v2 = s_pm[lane + 64], v3 = s_pm[lane + 96];
        float mx = fmaxf(fmaxf(v0, v1), fmaxf(v2, v3));
        #pragma unroll
        for (int o = 16; o >= 1; o >>= 1) mx = fmaxf(mx, __shfl_xor_sync(0xffffffffu, mx, o));
        float e0 = __expf(v0 - mx), e1 = __expf(v1 - mx);
        float e2 = __expf(v2 - mx), e3 = __expf(v3 - mx);
        float s = e0 + e1 + e2 + e3;
        #pragma unroll
        for (int o = 16; o >= 1; o >>= 1) s += __shfl_xor_sync(0xffffffffu, s, o);
        float inv = 1.f / s;
        p_s[lane] = e0 * inv; p_s[lane + 32] = e1 * inv;
        p_s[lane + 64] = e2 * inv; p_s[lane + 96] = e3 * inv;
    }
    __syncthreads();

    // ---- h_att = sum_j p_j h[j,:]; write segments 0 and 3 (coalesced) ----
    {
        const int jg = tid >> 6, dq = tid & 63;
        float4 acc = make_float4(0.f, 0.f, 0.f, 0.f);
        #pragma unroll 4
        for (int j = jg * 16; j < jg * 16 + 16; j++) {
            float4 hv = *(const float4*)(hrow + j * DN + dq * 4);
            float pj = p_s[j];
            acc.x += pj * hv.x; acc.y += pj * hv.y; acc.z += pj * hv.z; acc.w += pj * hv.w;
        }
        part[jg * 64 + dq] = acc;
        __syncthreads();
        if (tid < 64) {
            float4 sacc = part[tid];
            #pragma unroll
            for (int gg = 1; gg < 8; gg++) {
                float4 v = part[gg * 64 + tid];
                sacc.x += v.x; sacc.y += v.y; sacc.z += v.z; sacc.w += v.w;
            }
            part[tid] = sacc;
        }
        __syncthreads();
        const float4 ha = part[dq];
        #pragma unroll 2
        for (int j = jg * 16; j < jg * 16 + 16; j++) {
            float4 hv = *(const float4*)(hrow + j * DN + dq * 4);
            float4 o3;
            o3.x = hv.x * ha.x; o3.y = hv.y * ha.y; o3.z = hv.z * ha.z; o3.w = hv.w * ha.w;
            float* ob = out + outbase + (size_t)j * (4 * DN);
            *(float4*)(ob + dq * 4)           = hv;   // segment 0: h
            *(float4*)(ob + 3 * DN + dq * 4)  = o3;   // segment 3: h*h_att
        }
    }
}

// ---------------------------------------------------------------------------
extern "C" void kernel_launch(void* const* d_in, const int* in_sizes, int n_in,
                              void* d_out, int out_size)
{
    (void)in_sizes; (void)n_in; (void)out_size;
    const float* h = (const float*)d_in[0];
    const float* u = (const float*)d_in[1];
    const float* w = (const float*)d_in[2];
    // d_in[3] (scalar bias b) cancels in both softmaxes -> unused.
    float* out = (float*)d_out;

    cudaFuncSetAttribute(attn_h16, cudaFuncAttributeMaxDynamicSharedMemorySize, SMEM_BYTES);
    attn_h16<<<BB * MM, 512, SMEM_BYTES>>>(h, u, w, out);
}